// round 4
// baseline (speedup 1.0000x reference)
#include <cuda_runtime.h>
#include <math.h>

#define HH 1024
#define WW 1024
#define NPIX (HH * WW)
#define R_STRIP 8
#define BLK_B 256
#define PPT 8                              // pixels per thread in kernel B
#define TOTAL_B ((NPIX / PPT / BLK_B) * 2) // ticket count for finalize

__device__ unsigned char  g_edge[2][NPIX];  // edge flags (0/1)
__device__ unsigned short g_g[2][NPIX];     // row 1D distance (0xFFFF = featureless row)
__device__ float          g_sums[2];
__device__ unsigned int   g_count;

// ---------------------------------------------------------------------------
// Kernel A: strip-fused edges + row EDT with only TWO barriers per block.
// One 1024-thread block per (8-row strip, image).
//   load flags (strip + halo) -> sync
//   per-row horizontal AND cached in registers; edge = s && !(3x3 all-ones)
//   store all strip feats to sfeat -> sync
//   per-row outward scan (barrier-free) -> g (u16, 0xFFFF = featureless row)
// Also zeroes accumulators/ticket each graph replay.
// ---------------------------------------------------------------------------
__global__ void __launch_bounds__(WW) edges_row_kernel(
        const float* __restrict__ preds, const float* __restrict__ targets) {
    __shared__ unsigned char sflag[R_STRIP + 2][WW];
    __shared__ unsigned char sfeat[R_STRIP][WW];
    int img   = blockIdx.y;
    int strip = blockIdx.x;
    int j     = threadIdx.x;
    int y0    = strip * R_STRIP;
    if (img == 0 && strip == 0 && j < 3) {
        if (j < 2) g_sums[j] = 0.0f; else g_count = 0u;
    }
    const float* __restrict__ seg = (img == 0) ? preds : targets;
    #pragma unroll
    for (int rr = 0; rr < R_STRIP + 2; rr++) {
        int y = y0 + rr - 1;
        sflag[rr][j] = (y >= 0 && y < HH) ? (seg[y * WW + j] == 1.0f) : 0;
    }
    __syncthreads();
    // horizontal 3-AND per halo row, cached in registers
    unsigned char h[R_STRIP + 2];
    bool inj = (j > 0 && j < WW - 1);
    #pragma unroll
    for (int rr = 0; rr < R_STRIP + 2; rr++)
        h[rr] = inj ? (unsigned char)(sflag[rr][j - 1] & sflag[rr][j] & sflag[rr][j + 1]) : 0;
    #pragma unroll
    for (int rloc = 0; rloc < R_STRIP; rloc++) {
        int rs = rloc + 1;
        int y  = y0 + rloc;
        unsigned char s  = sflag[rs][j];
        unsigned char er = (y > 0 && y < HH - 1) ? (unsigned char)(h[rs - 1] & h[rs] & h[rs + 1]) : 0;
        unsigned char f  = (unsigned char)(s && !er);
        sfeat[rloc][j] = f;
        g_edge[img][y * WW + j] = f;
    }
    __syncthreads();
    #pragma unroll
    for (int rloc = 0; rloc < R_STRIP; rloc++) {
        const unsigned char* __restrict__ ft = sfeat[rloc];
        unsigned short gv;
        if (ft[j]) {
            gv = 0;
        } else {
            int r = 1;
            for (; r < WW; r++) {
                int jl = j - r, jr = j + r;
                if ((jl >= 0 && ft[jl]) || (jr < WW && ft[jr])) break;
            }
            gv = (r < WW) ? (unsigned short)r : (unsigned short)0xFFFF;
        }
        g_g[img][(y0 + rloc) * WW + j] = gv;
    }
}

// ---------------------------------------------------------------------------
// Kernel B: column lower-envelope min, 8 horizontal pixels per thread.
// One uint4 (8 x u16) load per neighbor row serves all 8 pixels. Group
// early-exit on max(best): extra iterations only test candidates
// >= r^2 >= best, so the min is exactly the reference's. Fused block
// reduction + ticket finalize -> sigmoid scalar.
// ---------------------------------------------------------------------------
__global__ void __launch_bounds__(BLK_B) col_reduce_finalize_kernel(float* __restrict__ out) {
    int img = blockIdx.y;
    int t = blockIdx.x * blockDim.x + threadIdx.x;   // 0 .. NPIX/8-1
    int idx8 = t * PPT;
    int j0 = idx8 & (WW - 1);
    int i  = idx8 >> 10;
    float val = 0.0f;
    uint2 w8 = *(const uint2*)&g_edge[1 - img][idx8];
    if (w8.x | w8.y) {
        const unsigned short* __restrict__ gg = g_g[img];
        unsigned char wa[8];
        *(uint2*)wa = w8;
        uint4 gv = *(const uint4*)&gg[idx8];
        const unsigned short* ga = (const unsigned short*)&gv;
        float best[8];
        float need = 0.0f;
        #pragma unroll
        for (int c = 0; c < 8; c++) {
            float gf = (ga[c] == 0xFFFFu) ? (1e6f - (float)(j0 + c)) : (float)ga[c];
            best[c] = wa[c] ? gf * gf : 0.0f;
            need = fmaxf(need, best[c]);
        }
        for (int r = 1; r < HH; r++) {
            float rr = (float)(r * r);
            if (rr >= need) break;
            int ku = i - r, kd = i + r;
            if (ku >= 0) {
                uint4 u = *(const uint4*)&gg[ku * WW + j0];
                const unsigned short* ua = (const unsigned short*)&u;
                #pragma unroll
                for (int c = 0; c < 8; c++) {
                    float f2 = (ua[c] == 0xFFFFu) ? (1e6f - (float)(j0 + c)) : (float)ua[c];
                    best[c] = fminf(best[c], f2 * f2 + rr);
                }
            }
            if (kd < HH) {
                uint4 u = *(const uint4*)&gg[kd * WW + j0];
                const unsigned short* ua = (const unsigned short*)&u;
                #pragma unroll
                for (int c = 0; c < 8; c++) {
                    float f2 = (ua[c] == 0xFFFFu) ? (1e6f - (float)(j0 + c)) : (float)ua[c];
                    best[c] = fminf(best[c], f2 * f2 + rr);
                }
            }
            need = 0.0f;
            #pragma unroll
            for (int c = 0; c < 8; c++) need = fmaxf(need, best[c]);
        }
        #pragma unroll
        for (int c = 0; c < 8; c++)
            if (wa[c]) val += sqrtf(best[c]);
    }
    // block reduction
    __shared__ float warpsum[BLK_B / 32];
    #pragma unroll
    for (int off = 16; off > 0; off >>= 1)
        val += __shfl_down_sync(0xffffffffu, val, off);
    int lane = threadIdx.x & 31;
    int wid  = threadIdx.x >> 5;
    if (lane == 0) warpsum[wid] = val;
    __syncthreads();
    if (wid == 0) {
        val = (lane < (BLK_B >> 5)) ? warpsum[lane] : 0.0f;
        #pragma unroll
        for (int off = 4; off > 0; off >>= 1)
            val += __shfl_down_sync(0xffffffffu, val, off);
        if (lane == 0) {
            atomicAdd(&g_sums[img], val);
            __threadfence();
            unsigned int tkt = atomicAdd(&g_count, 1u);
            if (tkt == (unsigned int)(TOTAL_B - 1)) {
                float s0 = atomicAdd(&g_sums[0], 0.0f);
                float s1 = atomicAdd(&g_sums[1], 0.0f);
                float invN = 1.0f / (float)NPIX;
                float loss = (s0 * invN + s1 * invN) * 0.5f;
                out[0] = 1.0f / (1.0f + expf(-loss));
            }
        }
    }
}

extern "C" void kernel_launch(void* const* d_in, const int* in_sizes, int n_in,
                              void* d_out, int out_size) {
    const float* preds   = (const float*)d_in[0];
    const float* targets = (const float*)d_in[1];
    float* out = (float*)d_out;

    edges_row_kernel<<<dim3(HH / R_STRIP, 2), dim3(WW)>>>(preds, targets);
    col_reduce_finalize_kernel<<<dim3(NPIX / PPT / BLK_B, 2), dim3(BLK_B)>>>(out);
}